// round 5
// baseline (speedup 1.0000x reference)
#include <cuda_runtime.h>
#include <cuda_bf16.h>
#include <stdint.h>

#define N_NODES  50000
#define N_EDGES  800000
#define F        128
#define N_GRAPHS 128
#define N_CLASSES 10

// ---------------- scratch (no allocations allowed) ----------------
__device__ __align__(16) float g_H[N_NODES * F];     // GEMM output
__device__ __align__(16) float g_ACC[N_NODES * F];   // aggregated layer output
__device__ float g_dinv[N_NODES];
__device__ int   g_degi[N_NODES];
__device__ int   g_rowbeg[N_NODES];
__device__ int   g_cursor[N_NODES];
__device__ int   g_alloc;
__device__ int   g_csrc[N_EDGES];
__device__ float g_cnorm[N_EDGES];
__device__ __align__(16) float g_gsum[N_GRAPHS * F];
__device__ float g_gcnt[N_GRAPHS];

__device__ __forceinline__ void red_add_v4(float* p, float4 v) {
    asm volatile("red.relaxed.gpu.global.add.v4.f32 [%0], {%1, %2, %3, %4};"
                 :: "l"(p), "f"(v.x), "f"(v.y), "f"(v.z), "f"(v.w)
                 : "memory");
}

__device__ __forceinline__ uint32_t f2tf(float v) {
    uint32_t r;
    asm("cvt.rna.tf32.f32 %0, %1;" : "=r"(r) : "f"(v));
    return r;
}

__device__ __forceinline__ void mma_tf32(float c[4], const uint32_t a[4],
                                         uint32_t b0, uint32_t b1) {
    asm volatile(
        "mma.sync.aligned.m16n8k8.row.col.f32.tf32.tf32.f32 "
        "{%0,%1,%2,%3}, {%4,%5,%6,%7}, {%8,%9}, {%0,%1,%2,%3};"
        : "+f"(c[0]), "+f"(c[1]), "+f"(c[2]), "+f"(c[3])
        : "r"(a[0]), "r"(a[1]), "r"(a[2]), "r"(a[3]), "r"(b0), "r"(b1));
}

// ---------------- precompute ----------------
__global__ void k_init(const int* __restrict__ batch) {
    int i = blockIdx.x * blockDim.x + threadIdx.x;
    if (i < N_NODES) {
        g_degi[i] = 0;
        atomicAdd(&g_gcnt[batch[i]], 1.0f);
    }
    if (i < N_GRAPHS * F) g_gsum[i] = 0.0f;
    if (i == 0) g_alloc = 0;
}

__global__ void k_zero_cnt() {
    int i = threadIdx.x;
    if (i < N_GRAPHS) g_gcnt[i] = 0.0f;
}

__global__ void k_deg(const int* __restrict__ ei) {
    int e = blockIdx.x * blockDim.x + threadIdx.x;
    if (e < N_EDGES) atomicAdd(&g_degi[ei[N_EDGES + e]], 1);
}

__global__ void k_alloc_seg() {
    int i = blockIdx.x * blockDim.x + threadIdx.x;
    if (i < N_NODES) {
        int deg = g_degi[i];
        g_dinv[i] = rsqrtf((float)deg + 1.0f);
        int pos = atomicAdd(&g_alloc, deg);
        g_rowbeg[i] = pos;
        g_cursor[i] = pos;
    }
}

__global__ void k_fill(const int* __restrict__ ei) {
    int e = blockIdx.x * blockDim.x + threadIdx.x;
    if (e < N_EDGES) {
        int s = ei[e];
        int d = ei[N_EDGES + e];
        int pos = atomicAdd(&g_cursor[d], 1);
        g_csrc[pos]  = s;
        g_cnorm[pos] = g_dinv[s] * g_dinv[d];
    }
}

// ---------------- GEMM: H = act(X) @ W  (tf32 MMA, error-compensated) ----------
// Tile: 64 rows x 128 cols, K=128. 256 threads = 8 warps (2 m x 4 n).
// smem: sX [64][132] row-major, sWT [128n][132k] (W transposed). Stride 132
// makes all fragment loads bank-conflict-free: (4*group + tig) mod 32 distinct.
#define XS 132
template <int MODE>
__global__ void __launch_bounds__(256, 2)
k_gemm(const float* __restrict__ Xin, const float* __restrict__ W) {
    extern __shared__ float smem[];
    float* sX  = smem;                 // 64*132
    float* sWT = smem + 64 * XS;       // 128*132

    const int tid   = threadIdx.x;
    const int row0  = blockIdx.x * 64;
    const int warp  = tid >> 5;
    const int lane  = tid & 31;
    const int group = lane >> 2;
    const int tig   = lane & 3;
    const int warp_m = warp & 1;       // 0..1  (32 rows each)
    const int warp_n = warp >> 1;      // 0..3  (32 cols each)

    // fill X tile (relu for MODE 1)
    const float* src = (MODE == 0) ? Xin : g_ACC;
    #pragma unroll
    for (int i = 0; i < 8; i++) {
        int idx = tid + i * 256;           // float4 index over 64*32
        int r   = idx >> 5;
        int c4  = idx & 31;
        int gr  = row0 + r;
        float4 v = make_float4(0.f, 0.f, 0.f, 0.f);
        if (gr < N_NODES) {
            v = ((const float4*)(src + (size_t)gr * F))[c4];
            if (MODE == 1) {
                v.x = fmaxf(v.x, 0.f); v.y = fmaxf(v.y, 0.f);
                v.z = fmaxf(v.z, 0.f); v.w = fmaxf(v.w, 0.f);
            }
        }
        *(float4*)&sX[r * XS + c4 * 4] = v;
    }

    // fill W transposed: sWT[n][k] = W[k][n]
    #pragma unroll
    for (int i = 0; i < 16; i++) {
        int idx = tid + i * 256;           // float4 index over 128*32
        int k   = idx >> 5;
        int n4  = (idx & 31) * 4;
        float4 v = ((const float4*)W)[idx];
        sWT[(n4 + 0) * XS + k] = v.x;
        sWT[(n4 + 1) * XS + k] = v.y;
        sWT[(n4 + 2) * XS + k] = v.z;
        sWT[(n4 + 3) * XS + k] = v.w;
    }
    __syncthreads();

    float acc[2][4][4];
    #pragma unroll
    for (int a = 0; a < 2; a++)
        #pragma unroll
        for (int b = 0; b < 4; b++)
            #pragma unroll
            for (int c = 0; c < 4; c++) acc[a][b][c] = 0.f;

    const int mb0 = warp_m * 32;
    const int nb0 = warp_n * 32;

    #pragma unroll 2
    for (int ks = 0; ks < 16; ks++) {
        const int k0 = ks * 8;
        uint32_t Ah[2][4], Al[2][4];
        #pragma unroll
        for (int mf = 0; mf < 2; mf++) {
            int base = (mb0 + mf * 16 + group) * XS + k0 + tig;
            float a0 = sX[base];
            float a1 = sX[base + 8 * XS];
            float a2 = sX[base + 4];
            float a3 = sX[base + 8 * XS + 4];
            Ah[mf][0] = f2tf(a0); Al[mf][0] = __float_as_uint(a0 - __uint_as_float(Ah[mf][0]));
            Ah[mf][1] = f2tf(a1); Al[mf][1] = __float_as_uint(a1 - __uint_as_float(Ah[mf][1]));
            Ah[mf][2] = f2tf(a2); Al[mf][2] = __float_as_uint(a2 - __uint_as_float(Ah[mf][2]));
            Ah[mf][3] = f2tf(a3); Al[mf][3] = __float_as_uint(a3 - __uint_as_float(Ah[mf][3]));
        }
        #pragma unroll
        for (int nf = 0; nf < 4; nf++) {
            int base = (nb0 + nf * 8 + group) * XS + k0 + tig;
            float b0 = sWT[base];
            float b1 = sWT[base + 4];
            uint32_t Bh0 = f2tf(b0), Bh1 = f2tf(b1);
            uint32_t Bl0 = __float_as_uint(b0 - __uint_as_float(Bh0));
            uint32_t Bl1 = __float_as_uint(b1 - __uint_as_float(Bh1));
            #pragma unroll
            for (int mf = 0; mf < 2; mf++) {
                mma_tf32(acc[mf][nf], Ah[mf], Bh0, Bh1);
                mma_tf32(acc[mf][nf], Ah[mf], Bl0, Bl1);
                mma_tf32(acc[mf][nf], Al[mf], Bh0, Bh1);
            }
        }
    }

    // epilogue: write H
    #pragma unroll
    for (int mf = 0; mf < 2; mf++) {
        int r = row0 + mb0 + mf * 16 + group;
        #pragma unroll
        for (int nf = 0; nf < 4; nf++) {
            int c = nb0 + nf * 8 + 2 * tig;
            if (r < N_NODES)
                *(float2*)&g_H[(size_t)r * F + c] =
                    make_float2(acc[mf][nf][0], acc[mf][nf][1]);
            if (r + 8 < N_NODES)
                *(float2*)&g_H[(size_t)(r + 8) * F + c] =
                    make_float2(acc[mf][nf][2], acc[mf][nf][3]);
        }
    }
}

// ---------------- aggregate: ACC[d] = sum_in norm*H[s] + dinv[d]^2*H[d] + b ----
template <int POOL>
__global__ void __launch_bounds__(256)
k_aggregate(const float* __restrict__ bias, const int* __restrict__ batch) {
    const int warp = (blockIdx.x * blockDim.x + threadIdx.x) >> 5;
    const int lane = threadIdx.x & 31;
    if (warp >= N_NODES) return;
    const int d = warp;

    const int beg = __ldg(&g_rowbeg[d]);
    const int end = beg + __ldg(&g_degi[d]);
    const float di = __ldg(&g_dinv[d]);

    float4 acc = *(const float4*)&g_H[(size_t)d * F + lane * 4];
    float sn = di * di;
    acc.x *= sn; acc.y *= sn; acc.z *= sn; acc.w *= sn;

    int j = beg;
    if (j < end) {
        int   s0 = __ldg(&g_csrc[j]);
        float n0 = __ldg(&g_cnorm[j]);
        float4 v0 = *(const float4*)&g_H[(size_t)s0 * F + lane * 4];
        for (j = beg + 1; j < end; j++) {
            int   s1 = __ldg(&g_csrc[j]);
            float n1 = __ldg(&g_cnorm[j]);
            float4 v1 = *(const float4*)&g_H[(size_t)s1 * F + lane * 4];
            acc.x += n0 * v0.x; acc.y += n0 * v0.y;
            acc.z += n0 * v0.z; acc.w += n0 * v0.w;
            v0 = v1; n0 = n1;
        }
        acc.x += n0 * v0.x; acc.y += n0 * v0.y;
        acc.z += n0 * v0.z; acc.w += n0 * v0.w;
    }

    float4 bv = *(const float4*)&bias[lane * 4];
    acc.x += bv.x; acc.y += bv.y; acc.z += bv.z; acc.w += bv.w;

    if (POOL) {
        int g = __ldg(&batch[d]);
        red_add_v4(&g_gsum[g * F + lane * 4], acc);
    } else {
        *(float4*)&g_ACC[(size_t)d * F + lane * 4] = acc;
    }
}

// ---------------- head ----------------
__global__ void k_final(const float* __restrict__ lin_w,
                        const float* __restrict__ lin_b,
                        float* __restrict__ out) {
    int g = blockIdx.x;
    int c = threadIdx.x;
    if (c >= N_CLASSES) return;
    float cnt = fmaxf(g_gcnt[g], 1.0f);
    float acc = 0.f;
    #pragma unroll 8
    for (int f = 0; f < F; f++)
        acc += g_gsum[g * F + f] * __ldg(&lin_w[f * N_CLASSES + c]);
    out[g * N_CLASSES + c] = acc / cnt + lin_b[c];
}

// ---------------- host ----------------
extern "C" void kernel_launch(void* const* d_in, const int* in_sizes, int n_in,
                              void* d_out, int out_size) {
    const float* x     = (const float*)d_in[0];
    const int*   ei    = (const int*)d_in[1];
    const int*   batch = (const int*)d_in[2];
    const float* w1 = (const float*)d_in[3];
    const float* b1 = (const float*)d_in[4];
    const float* w2 = (const float*)d_in[5];
    const float* b2 = (const float*)d_in[6];
    const float* w3 = (const float*)d_in[7];
    const float* b3 = (const float*)d_in[8];
    const float* lw = (const float*)d_in[9];
    const float* lb = (const float*)d_in[10];
    float* out = (float*)d_out;

    const int SMEM = (64 * XS + 128 * XS) * (int)sizeof(float);   // 101,376 B
    cudaFuncSetAttribute(k_gemm<0>, cudaFuncAttributeMaxDynamicSharedMemorySize, SMEM);
    cudaFuncSetAttribute(k_gemm<1>, cudaFuncAttributeMaxDynamicSharedMemorySize, SMEM);

    const int GB = (N_NODES + 63) / 64;
    const int AB = (N_NODES + 7) / 8;

    k_zero_cnt<<<1, N_GRAPHS>>>();
    k_init<<<(N_NODES + 255) / 256, 256>>>(batch);
    k_deg<<<(N_EDGES + 255) / 256, 256>>>(ei);
    k_alloc_seg<<<(N_NODES + 255) / 256, 256>>>();
    k_fill<<<(N_EDGES + 255) / 256, 256>>>(ei);

    k_gemm<0><<<GB, 256, SMEM>>>(x, w1);
    k_aggregate<0><<<AB, 256>>>(b1, batch);
    k_gemm<1><<<GB, 256, SMEM>>>(x, w2);
    k_aggregate<0><<<AB, 256>>>(b2, batch);
    k_gemm<1><<<GB, 256, SMEM>>>(x, w3);
    k_aggregate<1><<<AB, 256>>>(b3, batch);

    k_final<<<N_GRAPHS, 32>>>(lw, lb, out);
}

// round 6
// speedup vs baseline: 1.1443x; 1.1443x over previous
#include <cuda_runtime.h>
#include <cuda_bf16.h>
#include <stdint.h>

#define N_NODES  50000
#define N_EDGES  800000
#define F        128
#define N_GRAPHS 128
#define N_CLASSES 10

// ---------------- scratch (no allocations allowed) ----------------
__device__ __align__(16) float g_H[N_NODES * F];     // GEMM output
__device__ __align__(16) float g_ACC[N_NODES * F];   // aggregated layer output
__device__ float g_dinv[N_NODES];
__device__ int   g_degi[N_NODES];
__device__ int   g_rowbeg[N_NODES];
__device__ int   g_cursor[N_NODES];
__device__ int   g_alloc;
__device__ int   g_csrc[N_EDGES];
__device__ float g_cnorm[N_EDGES];
__device__ __align__(16) float g_gsum[N_GRAPHS * F];
__device__ float g_gcnt[N_GRAPHS];

__device__ __forceinline__ void red_add_v4(float* p, float4 v) {
    asm volatile("red.relaxed.gpu.global.add.v4.f32 [%0], {%1, %2, %3, %4};"
                 :: "l"(p), "f"(v.x), "f"(v.y), "f"(v.z), "f"(v.w)
                 : "memory");
}

// ---------------- packed f32x2 helpers (Blackwell FFMA2) ----------------
__device__ __forceinline__ unsigned long long pack2(float lo, float hi) {
    unsigned long long r;
    asm("mov.b64 %0, {%1, %2};" : "=l"(r) : "f"(lo), "f"(hi));
    return r;
}
__device__ __forceinline__ void fma2(unsigned long long& d,
                                     unsigned long long a, unsigned long long b) {
    asm("fma.rn.f32x2 %0, %1, %2, %0;" : "+l"(d) : "l"(a), "l"(b));
}
__device__ __forceinline__ float2 unpack2(unsigned long long v) {
    float2 r;
    asm("mov.b64 {%0, %1}, %2;" : "=f"(r.x), "=f"(r.y) : "l"(v));
    return r;
}

// ---------------- precompute ----------------
__global__ void k_init(const int* __restrict__ batch) {
    int i = blockIdx.x * blockDim.x + threadIdx.x;
    if (i < N_NODES) {
        g_degi[i] = 0;
        atomicAdd(&g_gcnt[batch[i]], 1.0f);
    }
    if (i < N_GRAPHS * F) g_gsum[i] = 0.0f;
    if (i == 0) g_alloc = 0;
}

__global__ void k_zero_cnt() {
    int i = threadIdx.x;
    if (i < N_GRAPHS) g_gcnt[i] = 0.0f;
}

__global__ void k_deg(const int* __restrict__ ei) {
    int e = blockIdx.x * blockDim.x + threadIdx.x;
    if (e < N_EDGES) atomicAdd(&g_degi[ei[N_EDGES + e]], 1);
}

__global__ void k_alloc_seg() {
    int i = blockIdx.x * blockDim.x + threadIdx.x;
    if (i < N_NODES) {
        int deg = g_degi[i];
        g_dinv[i] = rsqrtf((float)deg + 1.0f);
        int pos = atomicAdd(&g_alloc, deg);
        g_rowbeg[i] = pos;
        g_cursor[i] = pos;
    }
}

__global__ void k_fill(const int* __restrict__ ei) {
    int e = blockIdx.x * blockDim.x + threadIdx.x;
    if (e < N_EDGES) {
        int s = ei[e];
        int d = ei[N_EDGES + e];
        int pos = atomicAdd(&g_cursor[d], 1);
        g_csrc[pos]  = s;
        g_cnorm[pos] = g_dinv[s] * g_dinv[d];
    }
}

// ---------------- GEMM: H = act(X) @ W  (FFMA2 packed f32x2) ----------------
// MODE 0: read Xin (no relu). MODE 1: read relu(g_ACC).
// Block: 64 rows x 128 cols, 256 threads, full K=128 in smem.
template <int MODE>
__global__ void __launch_bounds__(256, 2)
k_gemm(const float* __restrict__ Xin, const float* __restrict__ W) {
    extern __shared__ float smem[];
    float* sW = smem;            // 128*128
    float* sX = smem + F * F;    // 64*128

    const int tid  = threadIdx.x;
    const int row0 = blockIdx.x * 64;

    #pragma unroll
    for (int i = 0; i < 16; i++)
        ((float4*)sW)[tid + i * 256] = ((const float4*)W)[tid + i * 256];

    const float* src = (MODE == 0) ? Xin : g_ACC;
    #pragma unroll
    for (int i = 0; i < 8; i++) {
        int idx = tid + i * 256;
        int r   = idx >> 5;
        int gr  = row0 + r;
        float4 v = make_float4(0.f, 0.f, 0.f, 0.f);
        if (gr < N_NODES) {
            v = ((const float4*)(src + (size_t)gr * F))[idx & 31];
            if (MODE == 1) {
                v.x = fmaxf(v.x, 0.f); v.y = fmaxf(v.y, 0.f);
                v.z = fmaxf(v.z, 0.f); v.w = fmaxf(v.w, 0.f);
            }
        }
        ((float4*)sX)[idx] = v;
    }
    __syncthreads();

    const int rg = tid >> 5;     // 0..7  (row group of 8)
    const int cg = tid & 31;     // 0..31 (4 cols each -> 2 f32x2 pairs)

    unsigned long long acc2[8][2];
    #pragma unroll
    for (int i = 0; i < 8; i++) {
        acc2[i][0] = 0ull;
        acc2[i][1] = 0ull;
    }

    #pragma unroll 4
    for (int k = 0; k < F; k += 4) {
        float4 w0 = *(float4*)&sW[(k + 0) * F + cg * 4];
        float4 w1 = *(float4*)&sW[(k + 1) * F + cg * 4];
        float4 w2 = *(float4*)&sW[(k + 2) * F + cg * 4];
        float4 w3 = *(float4*)&sW[(k + 3) * F + cg * 4];
        unsigned long long wl0 = pack2(w0.x, w0.y), wh0 = pack2(w0.z, w0.w);
        unsigned long long wl1 = pack2(w1.x, w1.y), wh1 = pack2(w1.z, w1.w);
        unsigned long long wl2 = pack2(w2.x, w2.y), wh2 = pack2(w2.z, w2.w);
        unsigned long long wl3 = pack2(w3.x, w3.y), wh3 = pack2(w3.z, w3.w);
        #pragma unroll
        for (int i = 0; i < 8; i++) {
            float4 xv = *(float4*)&sX[(rg * 8 + i) * F + k];
            unsigned long long xb;
            xb = pack2(xv.x, xv.x); fma2(acc2[i][0], xb, wl0); fma2(acc2[i][1], xb, wh0);
            xb = pack2(xv.y, xv.y); fma2(acc2[i][0], xb, wl1); fma2(acc2[i][1], xb, wh1);
            xb = pack2(xv.z, xv.z); fma2(acc2[i][0], xb, wl2); fma2(acc2[i][1], xb, wh2);
            xb = pack2(xv.w, xv.w); fma2(acc2[i][0], xb, wl3); fma2(acc2[i][1], xb, wh3);
        }
    }

    #pragma unroll
    for (int i = 0; i < 8; i++) {
        int r = row0 + rg * 8 + i;
        if (r < N_NODES) {
            float2 lo = unpack2(acc2[i][0]);
            float2 hi = unpack2(acc2[i][1]);
            *(float4*)&g_H[(size_t)r * F + cg * 4] =
                make_float4(lo.x, lo.y, hi.x, hi.y);
        }
    }
}

// ---------------- aggregate: ACC[d] = sum_in norm*H[s] + dinv[d]^2*H[d] + b ----
// POOL=1: instead of storing ACC, RED the result into g_gsum[batch[d]].
template <int POOL>
__global__ void __launch_bounds__(256)
k_aggregate(const float* __restrict__ bias, const int* __restrict__ batch) {
    const int warp = (blockIdx.x * blockDim.x + threadIdx.x) >> 5;
    const int lane = threadIdx.x & 31;
    if (warp >= N_NODES) return;
    const int d = warp;

    const int beg = __ldg(&g_rowbeg[d]);
    const int end = beg + __ldg(&g_degi[d]);
    const float di = __ldg(&g_dinv[d]);

    float4 acc = *(const float4*)&g_H[(size_t)d * F + lane * 4];
    float sn = di * di;
    acc.x *= sn; acc.y *= sn; acc.z *= sn; acc.w *= sn;

    int j = beg;
    if (j < end) {
        int   s0 = __ldg(&g_csrc[j]);
        float n0 = __ldg(&g_cnorm[j]);
        float4 v0 = *(const float4*)&g_H[(size_t)s0 * F + lane * 4];
        for (j = beg + 1; j < end; j++) {
            int   s1 = __ldg(&g_csrc[j]);
            float n1 = __ldg(&g_cnorm[j]);
            float4 v1 = *(const float4*)&g_H[(size_t)s1 * F + lane * 4];
            acc.x += n0 * v0.x; acc.y += n0 * v0.y;
            acc.z += n0 * v0.z; acc.w += n0 * v0.w;
            v0 = v1; n0 = n1;
        }
        acc.x += n0 * v0.x; acc.y += n0 * v0.y;
        acc.z += n0 * v0.z; acc.w += n0 * v0.w;
    }

    float4 bv = *(const float4*)&bias[lane * 4];
    acc.x += bv.x; acc.y += bv.y; acc.z += bv.z; acc.w += bv.w;

    if (POOL) {
        int g = __ldg(&batch[d]);
        red_add_v4(&g_gsum[g * F + lane * 4], acc);
    } else {
        *(float4*)&g_ACC[(size_t)d * F + lane * 4] = acc;
    }
}

// ---------------- head ----------------
__global__ void k_final(const float* __restrict__ lin_w,
                        const float* __restrict__ lin_b,
                        float* __restrict__ out) {
    int g = blockIdx.x;
    int c = threadIdx.x;
    if (c >= N_CLASSES) return;
    float cnt = fmaxf(g_gcnt[g], 1.0f);
    float acc = 0.f;
    #pragma unroll 8
    for (int f = 0; f < F; f++)
        acc += g_gsum[g * F + f] * __ldg(&lin_w[f * N_CLASSES + c]);
    out[g * N_CLASSES + c] = acc / cnt + lin_b[c];
}

// ---------------- host ----------------
extern "C" void kernel_launch(void* const* d_in, const int* in_sizes, int n_in,
                              void* d_out, int out_size) {
    const float* x     = (const float*)d_in[0];
    const int*   ei    = (const int*)d_in[1];
    const int*   batch = (const int*)d_in[2];
    const float* w1 = (const float*)d_in[3];
    const float* b1 = (const float*)d_in[4];
    const float* w2 = (const float*)d_in[5];
    const float* b2 = (const float*)d_in[6];
    const float* w3 = (const float*)d_in[7];
    const float* b3 = (const float*)d_in[8];
    const float* lw = (const float*)d_in[9];
    const float* lb = (const float*)d_in[10];
    float* out = (float*)d_out;

    const int SMEM = (F * F + 64 * F) * (int)sizeof(float);   // 96 KB
    cudaFuncSetAttribute(k_gemm<0>, cudaFuncAttributeMaxDynamicSharedMemorySize, SMEM);
    cudaFuncSetAttribute(k_gemm<1>, cudaFuncAttributeMaxDynamicSharedMemorySize, SMEM);

    const int GB = (N_NODES + 63) / 64;
    const int AB = (N_NODES + 7) / 8;

    k_zero_cnt<<<1, N_GRAPHS>>>();
    k_init<<<(N_NODES + 255) / 256, 256>>>(batch);
    k_deg<<<(N_EDGES + 255) / 256, 256>>>(ei);
    k_alloc_seg<<<(N_NODES + 255) / 256, 256>>>();
    k_fill<<<(N_EDGES + 255) / 256, 256>>>(ei);

    k_gemm<0><<<GB, 256, SMEM>>>(x, w1);
    k_aggregate<0><<<AB, 256>>>(b1, batch);
    k_gemm<1><<<GB, 256, SMEM>>>(x, w2);
    k_aggregate<0><<<AB, 256>>>(b2, batch);
    k_gemm<1><<<GB, 256, SMEM>>>(x, w3);
    k_aggregate<1><<<AB, 256>>>(b3, batch);

    k_final<<<N_GRAPHS, 32>>>(lw, lb, out);
}